// round 16
// baseline (speedup 1.0000x reference)
#include <cuda_runtime.h>

// out[b,s,e] = sum_h cs[b,s,e,h] * W[e,h] + bias[e]
// B=4, S=512, E=64, H=1024 -> ROWS = 131072 reductions over 1024 contiguous floats.
//
// FINAL KERNEL. Identical binary measured 6x: dur = 77.86/77.86/77.28/76.26/
// 77.98/77.92us (best 76.26); ncu kernel time 77.2-79.9us at 6756-7002 GB/s —
// the chip-side HBM rate wobbles ~3.5% run-to-run; the kernel tracks it at
// >=99% transport efficiency every run. Pure compulsory-traffic streaming:
// 512 MiB read once, 0.5 FLOP/byte. 10 structural/tuning variants (block
// 32/64/128/256, 128/256-bit LDG, row pairing, persistent grids,
// front-batching, cache hints) all collapse onto the DRAM rate; every other
// pipe <14% utilized. Nothing software-addressable remains (LTS cap is
// path-independent -> TMA is not a lever; channel hash/refresh are HW).
//
// Shape: one warp per CTA, one row per warp (fresh warp per row — per-warp
// tails hidden by co-resident warps; persistent loops serialize and regress),
// ld.global.cs for the one-pass stream, __ldg for the L1/L2-resident W row,
// SHFL-chain warp reduce.

#define E_DIM 64
#define H_DIM 1024
#define HV4   (H_DIM / 4)      // 256 float4 per row

__device__ __forceinline__ float4 ldcs_f4(const float4* p) {
    float4 v;
    asm volatile("ld.global.cs.v4.f32 {%0,%1,%2,%3}, [%4];"
                 : "=f"(v.x), "=f"(v.y), "=f"(v.z), "=f"(v.w)
                 : "l"(p));
    return v;
}

__global__ __launch_bounds__(32)
void Cell_to_Entity_78735340470739_kernel(
    const float4* __restrict__ cs,    // [ROWS, HV4]
    const float4* __restrict__ W,     // [E, HV4]
    const float*  __restrict__ bias,  // [E]
    float*        __restrict__ out)   // [ROWS]
{
    const int lane = threadIdx.x;         // 32-thread CTA = one warp
    const int row  = blockIdx.x;

    const int e = row & (E_DIM - 1);

    const float4* __restrict__ x = cs + (size_t)row * HV4;
    const float4* __restrict__ w = W  + (size_t)e   * HV4;

    float acc = 0.0f;
#pragma unroll
    for (int i = 0; i < 8; ++i) {
        const int idx = lane + 32 * i;
        float4 a = ldcs_f4(&x[idx]);   // streaming, evict-first: one-pass data
        float4 b = __ldg(&w[idx]);     // hot in L1/L2 (256 KiB total W)
        acc += a.x * b.x + a.y * b.y + a.z * b.z + a.w * b.w;
    }

    // warp reduction
#pragma unroll
    for (int off = 16; off > 0; off >>= 1)
        acc += __shfl_xor_sync(0xffffffffu, acc, off);

    if (lane == 0)
        out[row] = acc + __ldg(&bias[e]);
}

extern "C" void kernel_launch(void* const* d_in, const int* in_sizes, int n_in,
                              void* d_out, int out_size)
{
    const float4* cs   = (const float4*)d_in[0];   // [B,S,E,H] float32
    const float4* W    = (const float4*)d_in[1];   // [E,H]     float32
    const float*  bias = (const float*)d_in[2];    // [E]       float32
    float*        out  = (float*)d_out;            // [B,S,E]   float32

    const int rows = out_size;                     // B*S*E = 131072

    Cell_to_Entity_78735340470739_kernel<<<rows, 32>>>(cs, W, bias, out);
}

// round 17
// speedup vs baseline: 1.0008x; 1.0008x over previous
#include <cuda_runtime.h>

// out[b,s,e] = sum_h cs[b,s,e,h] * W[e,h] + bias[e]
// B=4, S=512, E=64, H=1024 -> ROWS = 131072 reductions over 1024 contiguous floats.
//
// FINAL KERNEL. Identical binary measured 7x: dur = 77.86/77.86/77.28/76.26/
// 77.98/77.92/77.92us (best 76.26); ncu kernel time 77.2-79.9us at
// 6756-7002 GB/s — the chip-side HBM rate wobbles ~3.5% run-to-run; the kernel
// tracks it at >=99% transport efficiency every run. Pure compulsory-traffic
// streaming: 512 MiB read once, 0.5 FLOP/byte. 10 structural/tuning variants
// (block 32/64/128/256, 128/256-bit LDG, row pairing, persistent grids,
// front-batching, cache hints) all collapse onto the DRAM rate; every other
// pipe <14% utilized. Nothing software-addressable remains (LTS cap is
// path-independent -> TMA is not a lever; channel hash/refresh are HW).
//
// Shape: one warp per CTA, one row per warp (fresh warp per row — per-warp
// tails hidden by co-resident warps; persistent loops serialize and regress),
// ld.global.cs for the one-pass stream, __ldg for the L1/L2-resident W row,
// SHFL-chain warp reduce.

#define E_DIM 64
#define H_DIM 1024
#define HV4   (H_DIM / 4)      // 256 float4 per row

__device__ __forceinline__ float4 ldcs_f4(const float4* p) {
    float4 v;
    asm volatile("ld.global.cs.v4.f32 {%0,%1,%2,%3}, [%4];"
                 : "=f"(v.x), "=f"(v.y), "=f"(v.z), "=f"(v.w)
                 : "l"(p));
    return v;
}

__global__ __launch_bounds__(32)
void Cell_to_Entity_78735340470739_kernel(
    const float4* __restrict__ cs,    // [ROWS, HV4]
    const float4* __restrict__ W,     // [E, HV4]
    const float*  __restrict__ bias,  // [E]
    float*        __restrict__ out)   // [ROWS]
{
    const int lane = threadIdx.x;         // 32-thread CTA = one warp
    const int row  = blockIdx.x;

    const int e = row & (E_DIM - 1);

    const float4* __restrict__ x = cs + (size_t)row * HV4;
    const float4* __restrict__ w = W  + (size_t)e   * HV4;

    float acc = 0.0f;
#pragma unroll
    for (int i = 0; i < 8; ++i) {
        const int idx = lane + 32 * i;
        float4 a = ldcs_f4(&x[idx]);   // streaming, evict-first: one-pass data
        float4 b = __ldg(&w[idx]);     // hot in L1/L2 (256 KiB total W)
        acc += a.x * b.x + a.y * b.y + a.z * b.z + a.w * b.w;
    }

    // warp reduction
#pragma unroll
    for (int off = 16; off > 0; off >>= 1)
        acc += __shfl_xor_sync(0xffffffffu, acc, off);

    if (lane == 0)
        out[row] = acc + __ldg(&bias[e]);
}

extern "C" void kernel_launch(void* const* d_in, const int* in_sizes, int n_in,
                              void* d_out, int out_size)
{
    const float4* cs   = (const float4*)d_in[0];   // [B,S,E,H] float32
    const float4* W    = (const float4*)d_in[1];   // [E,H]     float32
    const float*  bias = (const float*)d_in[2];    // [E]       float32
    float*        out  = (float*)d_out;            // [B,S,E]   float32

    const int rows = out_size;                     // B*S*E = 131072

    Cell_to_Entity_78735340470739_kernel<<<rows, 32>>>(cs, W, bias, out);
}